// round 8
// baseline (speedup 1.0000x reference)
#include <cuda_runtime.h>
#include <cuda_bf16.h>
#include <cstdint>
#include <math.h>

// ============================================================================
// Problem constants
// ============================================================================
#define NROWS 8192
#define DIM   1024

static __device__ uint8_t g_qn[NROWS * DIM];   // normalized queries, e4m3
static __device__ uint8_t g_nn[NROWS * DIM];   // normalized negatives, e4m3
static __device__ double g_sums[2];            // [0]=neg exp-sum, [1]=pos exp-sum

static constexpr float L2E = 1.4426950408889634f;    // log2(e)

// ============================================================================
// PTX helpers (target-independent: cp.async + ldmatrix + mma.sync fp8)
// ============================================================================
__device__ __forceinline__ uint32_t smem_to_u32(const void* smem_ptr) {
    uint32_t addr;
    asm("{ .reg .u64 tmp; cvta.to.shared.u64 tmp, %1; cvt.u32.u64 %0, tmp; }"
        : "=r"(addr) : "l"(smem_ptr));
    return addr;
}

__device__ __forceinline__ void cp_async16(uint32_t dst_smem, const void* src) {
    asm volatile("cp.async.cg.shared.global [%0], [%1], 16;"
                 :: "r"(dst_smem), "l"(__cvta_generic_to_global(src)) : "memory");
}
__device__ __forceinline__ void cp_async_commit() {
    asm volatile("cp.async.commit_group;" ::: "memory");
}
template <int N>
__device__ __forceinline__ void cp_async_wait() {
    asm volatile("cp.async.wait_group %0;" :: "n"(N) : "memory");
}

__device__ __forceinline__ void ldmatrix_x4(uint32_t& r0, uint32_t& r1,
                                            uint32_t& r2, uint32_t& r3,
                                            uint32_t addr) {
    asm volatile("ldmatrix.sync.aligned.m8n8.x4.shared.b16 {%0,%1,%2,%3}, [%4];"
                 : "=r"(r0), "=r"(r1), "=r"(r2), "=r"(r3) : "r"(addr));
}

// D = A(16x32, e4m3, row) * B(32x8, e4m3, col) + D, f32 accum
__device__ __forceinline__ void mma_fp8(float& c0, float& c1, float& c2, float& c3,
                                        uint32_t a0, uint32_t a1, uint32_t a2, uint32_t a3,
                                        uint32_t b0, uint32_t b1) {
    asm volatile(
        "mma.sync.aligned.m16n8k32.row.col.f32.e4m3.e4m3.f32 "
        "{%0,%1,%2,%3}, {%4,%5,%6,%7}, {%8,%9}, {%0,%1,%2,%3};"
        : "+f"(c0), "+f"(c1), "+f"(c2), "+f"(c3)
        : "r"(a0), "r"(a1), "r"(a2), "r"(a3), "r"(b0), "r"(b1));
}

// pack two f32 -> e4m3x2 (a -> upper byte, b -> lower byte)
__device__ __forceinline__ uint32_t pack_e4m3_4(float x0, float x1, float x2, float x3) {
    uint16_t lo, hi;
    asm("cvt.rn.satfinite.e4m3x2.f32 %0, %1, %2;" : "=h"(lo) : "f"(x1), "f"(x0));
    asm("cvt.rn.satfinite.e4m3x2.f32 %0, %1, %2;" : "=h"(hi) : "f"(x3), "f"(x2));
    return (uint32_t)lo | ((uint32_t)hi << 16);
}

#define SMEM_SWIZZLE_128B(byte_offset) \
    ((byte_offset) ^ (((byte_offset) >> 3) & 0x70))

// ============================================================================
// GEMM config: CTA tile 128x128, BK=128 e4m3 (128B rows, SW128), 3 stages,
// 256 threads (4x2 warps), 2 CTAs/SM.
// ============================================================================
static constexpr int BM = 128;
static constexpr int BN = 128;
static constexpr int BKB = 128;               // K bytes per tile = 128 e4m3
static constexpr int STAGES = 3;
static constexpr int NKT = DIM / BKB;         // 8 k-tiles
static constexpr int A_SZ = BM * BKB;         // 16384 B
static constexpr int B_SZ = BN * BKB;         // 16384 B
static constexpr int STAGE_SZ = A_SZ + B_SZ;  // 32768 B
static constexpr int DYN_SMEM = STAGES * STAGE_SZ;  // 98304 B

// ============================================================================
// Kernel 0: zero accumulators
// ============================================================================
__global__ void zero_kernel() {
    g_sums[0] = 0.0;
    g_sums[1] = 0.0;
}

// ============================================================================
// Kernel 1: fused normalize + positive diagonal.
//  block b <  NROWS: row b of q AND p -> norms + dot; write e4m3 q; pos term.
//  block b >= NROWS: normalize n row (b-NROWS) -> e4m3.
// ============================================================================
__global__ void __launch_bounds__(256) normalize_pos_kernel(
    const float* __restrict__ q, const float* __restrict__ p,
    const float* __restrict__ nneg) {
    int b = blockIdx.x;
    int t = threadIdx.x;
    __shared__ float ws[8], wd[8], wp[8];
    __shared__ float sinv;

    if (b >= NROWS) {                       // ---- negatives ----
        int row = b - NROWS;
        float4 v = reinterpret_cast<const float4*>(nneg + (size_t)row * DIM)[t];
        float ss = v.x * v.x + v.y * v.y + v.z * v.z + v.w * v.w;
        #pragma unroll
        for (int o = 16; o; o >>= 1) ss += __shfl_xor_sync(0xffffffffu, ss, o);
        if ((t & 31) == 0) ws[t >> 5] = ss;
        __syncthreads();
        if (t == 0) {
            float tot = 0.f;
            #pragma unroll
            for (int i = 0; i < 8; i++) tot += ws[i];
            sinv = 1.0f / fmaxf(sqrtf(tot), 1e-8f);
        }
        __syncthreads();
        float inv = sinv;
        reinterpret_cast<uint32_t*>(g_nn + (size_t)row * DIM)[t] =
            pack_e4m3_4(v.x * inv, v.y * inv, v.z * inv, v.w * inv);
    } else {                                // ---- queries + positives ----
        int row = b;
        float4 a = reinterpret_cast<const float4*>(q + (size_t)row * DIM)[t];
        float4 c = reinterpret_cast<const float4*>(p + (size_t)row * DIM)[t];
        float qq  = a.x * a.x + a.y * a.y + a.z * a.z + a.w * a.w;
        float pp  = c.x * c.x + c.y * c.y + c.z * c.z + c.w * c.w;
        float dot = a.x * c.x + a.y * c.y + a.z * c.z + a.w * c.w;
        #pragma unroll
        for (int o = 16; o; o >>= 1) {
            qq  += __shfl_xor_sync(0xffffffffu, qq, o);
            pp  += __shfl_xor_sync(0xffffffffu, pp, o);
            dot += __shfl_xor_sync(0xffffffffu, dot, o);
        }
        if ((t & 31) == 0) { ws[t >> 5] = qq; wp[t >> 5] = pp; wd[t >> 5] = dot; }
        __syncthreads();
        if (t == 0) {
            float Q = 0, P = 0, D = 0;
            #pragma unroll
            for (int i = 0; i < 8; i++) { Q += ws[i]; P += wp[i]; D += wd[i]; }
            float nq = fmaxf(sqrtf(Q), 1e-8f);
            float s  = D / (nq * fmaxf(sqrtf(P), 1e-8f));
            double e = exp((double)(s * s - 2.0f * s + 0.75f));
            atomicAdd(&g_sums[1], e);
            sinv = 1.0f / nq;
        }
        __syncthreads();
        float inv = sinv;
        reinterpret_cast<uint32_t*>(g_qn + (size_t)row * DIM)[t] =
            pack_e4m3_4(a.x * inv, a.y * inv, a.z * inv, a.w * inv);
    }
}

// ============================================================================
// Kernel 2: fused GEMM (q @ n^T, e4m3) + exp-circle-loss reduction
// ============================================================================
__device__ __forceinline__ void load_tile(uint32_t dyn_base, int stage,
                                          const uint8_t* aG,
                                          const uint8_t* bG,
                                          int kt, int tid) {
    uint32_t abase = dyn_base + (uint32_t)stage * STAGE_SZ;
    uint32_t bbase = abase + A_SZ;
    const uint8_t* asrc = aG + kt * BKB;
    const uint8_t* bsrc = bG + kt * BKB;
    // A: 128 rows x 8 x 16B granules = 1024 granules, 4 per thread
    #pragma unroll
    for (int i = 0; i < 4; i++) {
        int idx = tid + i * 256;
        int row = idx >> 3, g = idx & 7;
        uint32_t off = SMEM_SWIZZLE_128B((uint32_t)(row * 128 + g * 16));
        cp_async16(abase + off, asrc + (size_t)row * DIM + g * 16);
    }
    // B: same shape
    #pragma unroll
    for (int i = 0; i < 4; i++) {
        int idx = tid + i * 256;
        int row = idx >> 3, g = idx & 7;
        uint32_t off = SMEM_SWIZZLE_128B((uint32_t)(row * 128 + g * 16));
        cp_async16(bbase + off, bsrc + (size_t)row * DIM + g * 16);
    }
}

__global__ void __launch_bounds__(256, 2) retri_gemm_kernel() {
    extern __shared__ __align__(16) char dyn_smem[];
    __shared__ float s_wsum[8];

    const int tid  = threadIdx.x;
    const int wid  = tid >> 5;
    const int lane = tid & 31;
    const int wm   = wid & 3;       // warp M quadrant: rows wm*32
    const int wn   = wid >> 2;      // warp N half   : cols wn*64

    uint32_t dyn_base = smem_to_u32(dyn_smem);

    const int tileM = blockIdx.x & 63;
    const int tileN = blockIdx.x >> 6;
    const uint8_t* aG = g_qn + (size_t)tileM * BM * DIM;
    const uint8_t* bG = g_nn + (size_t)tileN * BN * DIM;

    // --- per-lane ldmatrix row constants (identical addressing to bf16:
    // fp8 k32 fragments are byte-isomorphic to bf16 k16 fragments) ---
    const int a_half = lane >> 4;
    uint32_t a_rowoff[2];
    uint32_t a_row7[2];
    #pragma unroll
    for (int mi = 0; mi < 2; mi++) {
        int r = wm * 32 + mi * 16 + (lane & 15);
        a_rowoff[mi] = (uint32_t)(r * 128);
        a_row7[mi]   = (uint32_t)(r & 7);
    }
    const int b_half = (lane >> 3) & 1;
    const int b_rl   = (lane & 7) + ((lane >> 4) & 1) * 8;
    uint32_t b_rowoff[4];
    uint32_t b_row7[4];
    #pragma unroll
    for (int nip = 0; nip < 4; nip++) {
        int r = wn * 64 + nip * 16 + b_rl;
        b_rowoff[nip] = (uint32_t)(r * 128);
        b_row7[nip]   = (uint32_t)(r & 7);
    }

    float c[2][8][4];
    #pragma unroll
    for (int mi = 0; mi < 2; mi++)
        #pragma unroll
        for (int ni = 0; ni < 8; ni++)
            #pragma unroll
            for (int e = 0; e < 4; e++) c[mi][ni][e] = 0.f;

    // --- prologue ---
    #pragma unroll
    for (int s = 0; s < STAGES - 1; s++) {
        load_tile(dyn_base, s, aG, bG, s, tid);
        cp_async_commit();
    }

    // --- main loop ---
    #pragma unroll 1
    for (int kt = 0; kt < NKT; kt++) {
        cp_async_wait<STAGES - 2>();
        __syncthreads();

        int nxt = kt + STAGES - 1;
        if (nxt < NKT)
            load_tile(dyn_base, nxt % STAGES, aG, bG, nxt, tid);
        cp_async_commit();

        uint32_t As = dyn_base + (uint32_t)(kt % STAGES) * STAGE_SZ;
        uint32_t Bs = As + A_SZ;

        #pragma unroll
        for (int j = 0; j < 4; j++) {           // 4 x k32 within BKB=128
            uint32_t a0[2], a1[2], a2[2], a3[2];
            #pragma unroll
            for (int mi = 0; mi < 2; mi++) {
                uint32_t ch = (uint32_t)(2 * j + a_half) ^ a_row7[mi];
                ldmatrix_x4(a0[mi], a1[mi], a2[mi], a3[mi],
                            As + a_rowoff[mi] + (ch << 4));
            }
            uint32_t bfr[8][2];
            #pragma unroll
            for (int nip = 0; nip < 4; nip++) {
                uint32_t ch = (uint32_t)(2 * j + b_half) ^ b_row7[nip];
                uint32_t r0, r1, r2, r3;
                ldmatrix_x4(r0, r1, r2, r3, Bs + b_rowoff[nip] + (ch << 4));
                bfr[2 * nip][0] = r0; bfr[2 * nip][1] = r1;
                bfr[2 * nip + 1][0] = r2; bfr[2 * nip + 1][1] = r3;
            }
            #pragma unroll
            for (int mi = 0; mi < 2; mi++)
                #pragma unroll
                for (int ni = 0; ni < 8; ni++)
                    mma_fp8(c[mi][ni][0], c[mi][ni][1], c[mi][ni][2], c[mi][ni][3],
                            a0[mi], a1[mi], a2[mi], a3[mi],
                            bfr[ni][0], bfr[ni][1]);
        }
        __syncthreads();
    }

    // --- epilogue: exp-transform + global reduce (no C store) ---
    float lsum = 0.f;
    #pragma unroll
    for (int mi = 0; mi < 2; mi++)
        #pragma unroll
        for (int ni = 0; ni < 8; ni++)
            #pragma unroll
            for (int e = 0; e < 4; e++) {
                float x  = c[mi][ni][e];                               // cosine sim
                float t2 = fmaf(x, fmaf(x, L2E, 2.f * L2E), 0.75f * L2E);
                lsum += exp2f(t2);
            }

    #pragma unroll
    for (int o = 16; o; o >>= 1) lsum += __shfl_xor_sync(0xffffffffu, lsum, o);
    if (lane == 0) s_wsum[wid] = lsum;
    __syncthreads();
    if (tid == 0) {
        float tot = 0.f;
        #pragma unroll
        for (int i = 0; i < 8; i++) tot += s_wsum[i];
        atomicAdd(&g_sums[0], (double)tot);
    }
}

// ============================================================================
// Kernel 3: out = softplus(log(sum_neg) + log(sum_pos))
// ============================================================================
__global__ void finish_kernel(float* out) {
    double z = log(g_sums[0]) + log(g_sums[1]);
    double r = (z > 0.0) ? z + log1p(exp(-z)) : log1p(exp(z));
    out[0] = (float)r;
}

// ============================================================================
// Launcher
// ============================================================================
extern "C" void kernel_launch(void* const* d_in, const int* in_sizes, int n_in,
                              void* d_out, int out_size) {
    (void)in_sizes; (void)n_in; (void)out_size;
    const float* q = (const float*)d_in[0];
    const float* p = (const float*)d_in[1];
    const float* n = (const float*)d_in[2];
    // d_in[3] (text_neg_index) is unused by the reference computation.
    float* out = (float*)d_out;

    cudaFuncSetAttribute(retri_gemm_kernel,
                         cudaFuncAttributeMaxDynamicSharedMemorySize, DYN_SMEM);

    zero_kernel<<<1, 32>>>();
    normalize_pos_kernel<<<2 * NROWS, 256>>>(q, p, n);
    retri_gemm_kernel<<<(NROWS / BM) * (NROWS / BN), 256, DYN_SMEM>>>();
    finish_kernel<<<1, 1>>>(out);
}

// round 10
// speedup vs baseline: 1.1218x; 1.1218x over previous
#include <cuda_runtime.h>
#include <cuda_bf16.h>
#include <cstdint>
#include <math.h>

// ============================================================================
// Problem constants
// ============================================================================
#define NROWS 8192
#define DIM   1024

static __device__ __nv_bfloat16 g_qn[NROWS * DIM];   // normalized queries, bf16
static __device__ __nv_bfloat16 g_nn[NROWS * DIM];   // normalized negatives, bf16
static __device__ double g_sums[2];                   // [0]=neg exp-sum, [1]=pos exp-sum

static constexpr float L2E = 1.4426950408889634f;    // log2(e)

// ============================================================================
// PTX helpers (target-independent: cp.async + ldmatrix + mma.sync only)
// ============================================================================
__device__ __forceinline__ uint32_t smem_to_u32(const void* smem_ptr) {
    uint32_t addr;
    asm("{ .reg .u64 tmp; cvta.to.shared.u64 tmp, %1; cvt.u32.u64 %0, tmp; }"
        : "=r"(addr) : "l"(smem_ptr));
    return addr;
}

__device__ __forceinline__ void cp_async16(uint32_t dst_smem, const void* src) {
    asm volatile("cp.async.cg.shared.global [%0], [%1], 16;"
                 :: "r"(dst_smem), "l"(__cvta_generic_to_global(src)) : "memory");
}
__device__ __forceinline__ void cp_async_commit() {
    asm volatile("cp.async.commit_group;" ::: "memory");
}
template <int N>
__device__ __forceinline__ void cp_async_wait() {
    asm volatile("cp.async.wait_group %0;" :: "n"(N) : "memory");
}

__device__ __forceinline__ void ldmatrix_x4(uint32_t& r0, uint32_t& r1,
                                            uint32_t& r2, uint32_t& r3,
                                            uint32_t addr) {
    asm volatile("ldmatrix.sync.aligned.m8n8.x4.shared.b16 {%0,%1,%2,%3}, [%4];"
                 : "=r"(r0), "=r"(r1), "=r"(r2), "=r"(r3) : "r"(addr));
}

// D = A(16x16, bf16, row) * B(16x8, bf16, col) + D, f32 accum
__device__ __forceinline__ void mma_bf16(float& c0, float& c1, float& c2, float& c3,
                                         uint32_t a0, uint32_t a1, uint32_t a2, uint32_t a3,
                                         uint32_t b0, uint32_t b1) {
    asm volatile(
        "mma.sync.aligned.m16n8k16.row.col.f32.bf16.bf16.f32 "
        "{%0,%1,%2,%3}, {%4,%5,%6,%7}, {%8,%9}, {%0,%1,%2,%3};"
        : "+f"(c0), "+f"(c1), "+f"(c2), "+f"(c3)
        : "r"(a0), "r"(a1), "r"(a2), "r"(a3), "r"(b0), "r"(b1));
}

#define SMEM_SWIZZLE_128B(byte_offset) \
    ((byte_offset) ^ (((byte_offset) >> 3) & 0x70))

// ============================================================================
// GEMM config: CTA tile 128x128, BK=64 bf16 (128B rows, SW128), 3 stages,
// 256 threads (4x2 warps), 2 CTAs/SM. Single __syncthreads per k-tile:
// in iter kt the load targets stage (kt+2)%3 == (kt-1)%3, and all warps'
// compute of stage kt-1 precedes the top sync of iter kt in program order,
// so the top barrier alone orders compute-before-overwrite.
// ============================================================================
static constexpr int BM = 128;
static constexpr int BN = 128;
static constexpr int BK = 64;                 // 128 bytes/row -> SW128 swizzle
static constexpr int STAGES = 3;
static constexpr int NKT = DIM / BK;          // 16 k-tiles
static constexpr int A_SZ = BM * BK * 2;      // 16384 B
static constexpr int B_SZ = BN * BK * 2;      // 16384 B
static constexpr int STAGE_SZ = A_SZ + B_SZ;  // 32768 B
static constexpr int DYN_SMEM = STAGES * STAGE_SZ;  // 98304 B

// ============================================================================
// Kernel 0: zero accumulators
// ============================================================================
__global__ void zero_kernel() {
    g_sums[0] = 0.0;
    g_sums[1] = 0.0;
}

// ============================================================================
// Kernel 1: fused normalize + positive diagonal.
//  block b <  NROWS: row b of q AND p -> norms + dot; write bf16 q; pos term.
//  block b >= NROWS: normalize n row (b-NROWS) -> bf16.
// ============================================================================
__global__ void __launch_bounds__(256) normalize_pos_kernel(
    const float* __restrict__ q, const float* __restrict__ p,
    const float* __restrict__ nneg) {
    int b = blockIdx.x;
    int t = threadIdx.x;
    __shared__ float ws[8], wd[8], wp[8];
    __shared__ float sinv;

    if (b >= NROWS) {                       // ---- negatives ----
        int row = b - NROWS;
        float4 v = reinterpret_cast<const float4*>(nneg + (size_t)row * DIM)[t];
        float ss = v.x * v.x + v.y * v.y + v.z * v.z + v.w * v.w;
        #pragma unroll
        for (int o = 16; o; o >>= 1) ss += __shfl_xor_sync(0xffffffffu, ss, o);
        if ((t & 31) == 0) ws[t >> 5] = ss;
        __syncthreads();
        if (t == 0) {
            float tot = 0.f;
            #pragma unroll
            for (int i = 0; i < 8; i++) tot += ws[i];
            sinv = 1.0f / fmaxf(sqrtf(tot), 1e-8f);
        }
        __syncthreads();
        float inv = sinv;
        __nv_bfloat162* d2 = reinterpret_cast<__nv_bfloat162*>(g_nn + (size_t)row * DIM);
        d2[2 * t]     = __float22bfloat162_rn(make_float2(v.x * inv, v.y * inv));
        d2[2 * t + 1] = __float22bfloat162_rn(make_float2(v.z * inv, v.w * inv));
    } else {                                // ---- queries + positives ----
        int row = b;
        float4 a = reinterpret_cast<const float4*>(q + (size_t)row * DIM)[t];
        float4 c = reinterpret_cast<const float4*>(p + (size_t)row * DIM)[t];
        float qq  = a.x * a.x + a.y * a.y + a.z * a.z + a.w * a.w;
        float pp  = c.x * c.x + c.y * c.y + c.z * c.z + c.w * c.w;
        float dot = a.x * c.x + a.y * c.y + a.z * c.z + a.w * c.w;
        #pragma unroll
        for (int o = 16; o; o >>= 1) {
            qq  += __shfl_xor_sync(0xffffffffu, qq, o);
            pp  += __shfl_xor_sync(0xffffffffu, pp, o);
            dot += __shfl_xor_sync(0xffffffffu, dot, o);
        }
        if ((t & 31) == 0) { ws[t >> 5] = qq; wp[t >> 5] = pp; wd[t >> 5] = dot; }
        __syncthreads();
        if (t == 0) {
            float Q = 0, P = 0, D = 0;
            #pragma unroll
            for (int i = 0; i < 8; i++) { Q += ws[i]; P += wp[i]; D += wd[i]; }
            float nq = fmaxf(sqrtf(Q), 1e-8f);
            float s  = D / (nq * fmaxf(sqrtf(P), 1e-8f));
            double e = exp((double)(s * s - 2.0f * s + 0.75f));
            atomicAdd(&g_sums[1], e);
            sinv = 1.0f / nq;
        }
        __syncthreads();
        float inv = sinv;
        __nv_bfloat162* d2 = reinterpret_cast<__nv_bfloat162*>(g_qn + (size_t)row * DIM);
        d2[2 * t]     = __float22bfloat162_rn(make_float2(a.x * inv, a.y * inv));
        d2[2 * t + 1] = __float22bfloat162_rn(make_float2(a.z * inv, a.w * inv));
    }
}

// ============================================================================
// Kernel 2: fused GEMM (q @ n^T) + exp-circle-loss reduction (mma.sync bf16)
// ============================================================================
__device__ __forceinline__ void load_tile(uint32_t dyn_base, int stage,
                                          const __nv_bfloat16* aG,
                                          const __nv_bfloat16* bG,
                                          int kt, int tid) {
    uint32_t abase = dyn_base + (uint32_t)stage * STAGE_SZ;
    uint32_t bbase = abase + A_SZ;
    const __nv_bfloat16* asrc = aG + kt * BK;
    const __nv_bfloat16* bsrc = bG + kt * BK;
    // A: 128 rows x 8 x 16B granules = 1024 granules, 4 per thread
    #pragma unroll
    for (int i = 0; i < 4; i++) {
        int idx = tid + i * 256;
        int row = idx >> 3, g = idx & 7;
        uint32_t off = SMEM_SWIZZLE_128B((uint32_t)(row * 128 + g * 16));
        cp_async16(abase + off, asrc + (size_t)row * DIM + g * 8);
    }
    // B: same shape
    #pragma unroll
    for (int i = 0; i < 4; i++) {
        int idx = tid + i * 256;
        int row = idx >> 3, g = idx & 7;
        uint32_t off = SMEM_SWIZZLE_128B((uint32_t)(row * 128 + g * 16));
        cp_async16(bbase + off, bsrc + (size_t)row * DIM + g * 8);
    }
}

__global__ void __launch_bounds__(256, 2) retri_gemm_kernel() {
    extern __shared__ __align__(16) char dyn_smem[];
    __shared__ float s_wsum[8];

    const int tid  = threadIdx.x;
    const int wid  = tid >> 5;
    const int lane = tid & 31;
    const int wm   = wid & 3;       // warp M quadrant: rows wm*32
    const int wn   = wid >> 2;      // warp N half   : cols wn*64

    uint32_t dyn_base = smem_to_u32(dyn_smem);

    const int tileM = blockIdx.x & 63;
    const int tileN = blockIdx.x >> 6;
    const __nv_bfloat16* aG = g_qn + (size_t)tileM * BM * DIM;
    const __nv_bfloat16* bG = g_nn + (size_t)tileN * BN * DIM;

    // --- per-lane ldmatrix row constants ---
    const int a_half = lane >> 4;
    uint32_t a_rowoff[2];
    uint32_t a_row7[2];
    #pragma unroll
    for (int mi = 0; mi < 2; mi++) {
        int r = wm * 32 + mi * 16 + (lane & 15);
        a_rowoff[mi] = (uint32_t)(r * 128);
        a_row7[mi]   = (uint32_t)(r & 7);
    }
    const int b_half = (lane >> 3) & 1;
    const int b_rl   = (lane & 7) + ((lane >> 4) & 1) * 8;
    uint32_t b_rowoff[4];
    uint32_t b_row7[4];
    #pragma unroll
    for (int nip = 0; nip < 4; nip++) {
        int r = wn * 64 + nip * 16 + b_rl;
        b_rowoff[nip] = (uint32_t)(r * 128);
        b_row7[nip]   = (uint32_t)(r & 7);
    }

    float c[2][8][4];
    #pragma unroll
    for (int mi = 0; mi < 2; mi++)
        #pragma unroll
        for (int ni = 0; ni < 8; ni++)
            #pragma unroll
            for (int e = 0; e < 4; e++) c[mi][ni][e] = 0.f;

    // --- prologue: stages 0..STAGES-2 ---
    #pragma unroll
    for (int s = 0; s < STAGES - 1; s++) {
        load_tile(dyn_base, s, aG, bG, s, tid);
        cp_async_commit();
    }

    // --- main loop: ONE barrier per k-tile ---
    #pragma unroll 1
    for (int kt = 0; kt < NKT; kt++) {
        cp_async_wait<STAGES - 2>();
        __syncthreads();

        int nxt = kt + STAGES - 1;
        if (nxt < NKT)
            load_tile(dyn_base, nxt % STAGES, aG, bG, nxt, tid);
        cp_async_commit();

        uint32_t As = dyn_base + (uint32_t)(kt % STAGES) * STAGE_SZ;
        uint32_t Bs = As + A_SZ;

        #pragma unroll
        for (int j = 0; j < 4; j++) {           // 4 x k16 within BK=64
            uint32_t a0[2], a1[2], a2[2], a3[2];
            #pragma unroll
            for (int mi = 0; mi < 2; mi++) {
                uint32_t ch = (uint32_t)(2 * j + a_half) ^ a_row7[mi];
                ldmatrix_x4(a0[mi], a1[mi], a2[mi], a3[mi],
                            As + a_rowoff[mi] + (ch << 4));
            }
            uint32_t bfr[8][2];
            #pragma unroll
            for (int nip = 0; nip < 4; nip++) {
                uint32_t ch = (uint32_t)(2 * j + b_half) ^ b_row7[nip];
                uint32_t r0, r1, r2, r3;
                ldmatrix_x4(r0, r1, r2, r3, Bs + b_rowoff[nip] + (ch << 4));
                bfr[2 * nip][0] = r0; bfr[2 * nip][1] = r1;
                bfr[2 * nip + 1][0] = r2; bfr[2 * nip + 1][1] = r3;
            }
            #pragma unroll
            for (int mi = 0; mi < 2; mi++)
                #pragma unroll
                for (int ni = 0; ni < 8; ni++)
                    mma_bf16(c[mi][ni][0], c[mi][ni][1], c[mi][ni][2], c[mi][ni][3],
                             a0[mi], a1[mi], a2[mi], a3[mi],
                             bfr[ni][0], bfr[ni][1]);
        }
        // no bottom barrier: top barrier of the next iteration provides the
        // ordering (see config comment)
    }

    // --- epilogue: exp-transform + global reduce (no C store) ---
    float lsum = 0.f;
    #pragma unroll
    for (int mi = 0; mi < 2; mi++)
        #pragma unroll
        for (int ni = 0; ni < 8; ni++)
            #pragma unroll
            for (int e = 0; e < 4; e++) {
                float x  = c[mi][ni][e];                               // cosine sim
                float t2 = fmaf(x, fmaf(x, L2E, 2.f * L2E), 0.75f * L2E);
                lsum += exp2f(t2);
            }

    #pragma unroll
    for (int o = 16; o; o >>= 1) lsum += __shfl_xor_sync(0xffffffffu, lsum, o);
    if (lane == 0) s_wsum[wid] = lsum;
    __syncthreads();
    if (tid == 0) {
        float tot = 0.f;
        #pragma unroll
        for (int i = 0; i < 8; i++) tot += s_wsum[i];
        atomicAdd(&g_sums[0], (double)tot);
    }
}

// ============================================================================
// Kernel 3: out = softplus(log(sum_neg) + log(sum_pos))
// ============================================================================
__global__ void finish_kernel(float* out) {
    double z = log(g_sums[0]) + log(g_sums[1]);
    double r = (z > 0.0) ? z + log1p(exp(-z)) : log1p(exp(z));
    out[0] = (float)r;
}

// ============================================================================
// Launcher
// ============================================================================
extern "C" void kernel_launch(void* const* d_in, const int* in_sizes, int n_in,
                              void* d_out, int out_size) {
    (void)in_sizes; (void)n_in; (void)out_size;
    const float* q = (const float*)d_in[0];
    const float* p = (const float*)d_in[1];
    const float* n = (const float*)d_in[2];
    // d_in[3] (text_neg_index) is unused by the reference computation.
    float* out = (float*)d_out;

    cudaFuncSetAttribute(retri_gemm_kernel,
                         cudaFuncAttributeMaxDynamicSharedMemorySize, DYN_SMEM);

    zero_kernel<<<1, 32>>>();
    normalize_pos_kernel<<<2 * NROWS, 256>>>(q, p, n);
    retri_gemm_kernel<<<(NROWS / BM) * (NROWS / BN), 256, DYN_SMEM>>>();
    finish_kernel<<<1, 1>>>(out);
}